// round 4
// baseline (speedup 1.0000x reference)
#include <cuda_runtime.h>
#include <cuda_bf16.h>
#include <math.h>

// ---------------------------------------------------------------------------
// YOLO v5 loss (nc=1): B=64, N=32, A=3, grids 160/80/40, channels A*(5+1)=18.
// Strategy:
//   K_obj  : dense sum of softplus over the 3 obj planes only (1/6 of data).
//            Per-block partial sums to fixed slots (deterministic, no atomics).
//   K_final: single block. Per-target anchor match + in-warp dedup
//            (__match_any_sync, last-n wins), gather 5 floats per positive,
//            reduce everything, combine with dense partials in double.
// ---------------------------------------------------------------------------

#define NB2 1184          // 148 SMs * 8
#define NT2 256

// per-scale sizes
#define G0 160
#define G1 80
#define G2 40
#define HW4_0 6400        // (160*160)/4
#define HW4_1 1600
#define HW4_2 400
#define F4_0 1228800      // 64*3*HW4_0
#define F4_1 307200
#define F4_2 76800
#define F4_TOT (F4_0 + F4_1 + F4_2)

__device__ float g_part[NB2 * 3];   // per-block partial softplus sums (log2 units)

__device__ __forceinline__ float sp_log2(float x) {
    // log2(1 + exp(x));  |x| <~ 6 for N(0,1) inputs, no overflow concerns
    float e, l;
    asm("ex2.approx.ftz.f32 %0, %1;" : "=f"(e) : "f"(x * 1.4426950408889634f));
    asm("lg2.approx.ftz.f32 %0, %1;" : "=f"(l) : "f"(1.0f + e));
    return l;
}

__device__ __forceinline__ float softplusf(float x) {
    return __logf(1.0f + __expf(x));
}

__global__ void __launch_bounds__(NT2)
k_obj(const float4* __restrict__ p0, const float4* __restrict__ p1,
      const float4* __restrict__ p2)
{
    float a0 = 0.f, a1 = 0.f, a2 = 0.f;
    const int stride = NB2 * NT2;
    for (int f = blockIdx.x * NT2 + threadIdx.x; f < F4_TOT; f += stride) {
        if (f < F4_0) {
            int plane = f / HW4_0;
            int off   = f - plane * HW4_0;
            float4 v = __ldg(p0 + (plane * 6 + 4) * HW4_0 + off);
            a0 += sp_log2(v.x) + sp_log2(v.y) + sp_log2(v.z) + sp_log2(v.w);
        } else if (f < F4_0 + F4_1) {
            int g = f - F4_0;
            int plane = g / HW4_1;
            int off   = g - plane * HW4_1;
            float4 v = __ldg(p1 + (plane * 6 + 4) * HW4_1 + off);
            a1 += sp_log2(v.x) + sp_log2(v.y) + sp_log2(v.z) + sp_log2(v.w);
        } else {
            int g = f - (F4_0 + F4_1);
            int plane = g / HW4_2;
            int off   = g - plane * HW4_2;
            float4 v = __ldg(p2 + (plane * 6 + 4) * HW4_2 + off);
            a2 += sp_log2(v.x) + sp_log2(v.y) + sp_log2(v.z) + sp_log2(v.w);
        }
    }
    // warp reduce
    #pragma unroll
    for (int o = 16; o; o >>= 1) {
        a0 += __shfl_xor_sync(0xffffffffu, a0, o);
        a1 += __shfl_xor_sync(0xffffffffu, a1, o);
        a2 += __shfl_xor_sync(0xffffffffu, a2, o);
    }
    __shared__ float sh[3][NT2 / 32];
    int w = threadIdx.x >> 5, l = threadIdx.x & 31;
    if (l == 0) { sh[0][w] = a0; sh[1][w] = a1; sh[2][w] = a2; }
    __syncthreads();
    if (threadIdx.x == 0) {
        float s0 = 0.f, s1 = 0.f, s2 = 0.f;
        #pragma unroll
        for (int i = 0; i < NT2 / 32; i++) { s0 += sh[0][i]; s1 += sh[1][i]; s2 += sh[2][i]; }
        g_part[blockIdx.x * 3 + 0] = s0;
        g_part[blockIdx.x * 3 + 1] = s1;
        g_part[blockIdx.x * 3 + 2] = s2;
    }
}

__global__ void __launch_bounds__(1024)
k_final(const float* __restrict__ pr0, const float* __restrict__ pr1,
        const float* __restrict__ pr2, const float4* __restrict__ boxes,
        const float* __restrict__ anch, float* __restrict__ out)
{
    const int tid  = threadIdx.x;
    const int lane = tid & 31;
    const int warp = tid >> 5;

    // accumulators per scale: sq, softplus(-po), softplus(po), n_pos
    float sq[3]  = {0.f, 0.f, 0.f};
    float spn[3] = {0.f, 0.f, 0.f};
    float spp[3] = {0.f, 0.f, 0.f};
    float np[3]  = {0.f, 0.f, 0.f};

    // two (b,n) pairs per thread: p = tid and tid+1024
    float4 bx[2];
    bx[0] = __ldg(boxes + tid);
    bx[1] = __ldg(boxes + tid + 1024);

    // anchors [3][3][2]
    float A_[3][6];
    #pragma unroll
    for (int s = 0; s < 3; s++)
        #pragma unroll
        for (int j = 0; j < 6; j++)
            A_[s][j] = __ldg(anch + s * 6 + j);

    #pragma unroll
    for (int s = 0; s < 3; s++) {
        const float* pred = (s == 0) ? pr0 : ((s == 1) ? pr1 : pr2);
        const int   G  = (s == 0) ? G0 : ((s == 1) ? G1 : G2);
        const float Gf = (float)G;
        const int   HW = G * G;

        #pragma unroll
        for (int u = 0; u < 2; u++) {
            const int p = tid + u * 1024;
            const float gx = bx[u].x * Gf, gy = bx[u].y * Gf;
            const float gw = bx[u].z * Gf, gh = bx[u].w * Gf;

            // anchor matching: argmax_a prod(min(r, 1/r)), first-max wins
            int best = 0;
            float best_iou = -1.f, aw = 1.f, ah = 1.f;
            #pragma unroll
            for (int a = 0; a < 3; a++) {
                const float Aw = A_[s][2 * a], Ah = A_[s][2 * a + 1];
                const float iw = fminf(Aw / gw, gw / Aw);
                const float ih = fminf(Ah / gh, gh / Ah);
                const float io = iw * ih;
                if (io > best_iou) { best_iou = io; best = a; aw = Aw; ah = Ah; }
            }
            const int gi = (int)gx, gj = (int)gy;
            const int key = (best * G + gj) * G + gi;

            // in-warp dedup: lanes of this warp are exactly the 32 boxes of
            // one batch image. JAX scatter applies updates in order -> last n
            // (= highest lane) wins; n_pos counts unique cells.
            const unsigned m = __match_any_sync(0xffffffffu, key);
            const bool alive = (lane == 31 - __clz(m));

            if (alive) {
                const int b = p >> 5;
                const int base = ((b * 18 + best * 6) * G + gj) * G + gi;
                const float q0 = __ldg(pred + base);
                const float q1 = __ldg(pred + base + HW);
                const float q2 = __ldg(pred + base + 2 * HW);
                const float q3 = __ldg(pred + base + 3 * HW);
                const float po = __ldg(pred + base + 4 * HW);

                const float tx = gx - (float)gi;
                const float ty = gy - (float)gj;
                const float tw = logf(gw / aw + 1e-16f);
                const float th = logf(gh / ah + 1e-16f);

                const float d0 = q0 - tx, d1 = q1 - ty, d2 = q2 - tw, d3 = q3 - th;
                sq[s]  += d0 * d0 + d1 * d1 + d2 * d2 + d3 * d3;
                spn[s] += softplusf(-po);
                spp[s] += softplusf(po);
                np[s]  += 1.f;
            }
        }
    }

    // fold in the dense per-block partials (log2 units)
    float part[3] = {0.f, 0.f, 0.f};
    for (int i = tid; i < NB2; i += 1024) {
        part[0] += g_part[3 * i + 0];
        part[1] += g_part[3 * i + 1];
        part[2] += g_part[3 * i + 2];
    }

    // reduce 15 values across the block
    float vals[15];
    #pragma unroll
    for (int s = 0; s < 3; s++) {
        vals[s]      = sq[s];
        vals[3 + s]  = spn[s];
        vals[6 + s]  = spp[s];
        vals[9 + s]  = np[s];
        vals[12 + s] = part[s];
    }
    #pragma unroll
    for (int v = 0; v < 15; v++)
        #pragma unroll
        for (int o = 16; o; o >>= 1)
            vals[v] += __shfl_xor_sync(0xffffffffu, vals[v], o);

    __shared__ float sh[15][32];
    if (lane == 0)
        #pragma unroll
        for (int v = 0; v < 15; v++) sh[v][warp] = vals[v];
    __syncthreads();

    if (warp == 0) {
        float t[15];
        #pragma unroll
        for (int v = 0; v < 15; v++) {
            t[v] = sh[v][lane];
            #pragma unroll
            for (int o = 16; o; o >>= 1)
                t[v] += __shfl_xor_sync(0xffffffffu, t[v], o);
        }
        if (lane == 0) {
            const double T[3] = {4915200.0, 1228800.0, 307200.0};
            double lbox = 0.0, lobj = 0.0;
            #pragma unroll
            for (int s = 0; s < 3; s++) {
                const double npos = (double)t[9 + s];
                const double nneg = T[s] - npos;
                const double all_sp = (double)t[12 + s] * 0.6931471805599453; // ln2
                lobj += (double)t[3 + s] / npos + (all_sp - (double)t[6 + s]) / nneg;
                lbox += (double)t[0 + s] / npos;
            }
            out[0] = (float)(0.05 * lbox + 1.0 * lobj);
        }
    }
}

extern "C" void kernel_launch(void* const* d_in, const int* in_sizes, int n_in,
                              void* d_out, int out_size)
{
    (void)in_sizes; (void)n_in; (void)out_size;
    const float* pred0 = (const float*)d_in[0];
    const float* pred1 = (const float*)d_in[1];
    const float* pred2 = (const float*)d_in[2];
    const float* boxes = (const float*)d_in[3];
    // d_in[4] = labels (unused, nc == 1)
    const float* anch  = (const float*)d_in[5];
    float* out = (float*)d_out;

    k_obj<<<NB2, NT2>>>((const float4*)pred0, (const float4*)pred1,
                        (const float4*)pred2);
    k_final<<<1, 1024>>>(pred0, pred1, pred2, (const float4*)boxes, anch, out);
}

// round 5
// speedup vs baseline: 1.5204x; 1.5204x over previous
#include <cuda_runtime.h>
#include <cuda_bf16.h>
#include <math.h>

// ---------------------------------------------------------------------------
// YOLO v5 loss (nc=1): B=64, N=32, A=3, grids 160/80/40, channels A*(5+1)=18.
//   K1 (grid NB2+64): blocks [0,NB2)   -> dense softplus over the 3 obj planes
//                     blocks [NB2,+64) -> 1 warp each: sparse targets for one
//                                         batch image (match + dedup + gather)
//   K2 (1 block)    : fold dense partials + sparse partials, combine in double.
// ---------------------------------------------------------------------------

#define NB2 1184          // dense blocks: 148 SMs * 8
#define NT2 256

#define G0 160
#define G1 80
#define G2 40
#define HW4_0 6400        // (160*160)/4
#define HW4_1 1600
#define HW4_2 400
#define F4_0 1228800      // 64*3*HW4_0
#define F4_1 307200
#define F4_2 76800
#define F4_TOT (F4_0 + F4_1 + F4_2)

__device__ float g_part[NB2 * 3];   // dense per-block partial sums (log2 units)
__device__ float g_sp[12 * 64];     // sparse per-image sums, SoA [12][64]
// v: 0..2 sq, 3..5 spn, 6..8 spp, 9..11 npos (per scale)

__device__ __forceinline__ float sp_log2(float x) {
    // log2(1 + exp(x)); |x| <~ 6 for N(0,1) inputs
    float e, l;
    asm("ex2.approx.ftz.f32 %0, %1;" : "=f"(e) : "f"(x * 1.4426950408889634f));
    asm("lg2.approx.ftz.f32 %0, %1;" : "=f"(l) : "f"(1.0f + e));
    return l;
}

__device__ __forceinline__ float softplus_fast(float x) {
    return sp_log2(x) * 0.6931471805599453f;   // ln2
}

// ------------------------- sparse: one warp = one image ---------------------
__device__ __forceinline__ void sparse_warp(
    int b, const float* __restrict__ pr0, const float* __restrict__ pr1,
    const float* __restrict__ pr2, const float4* __restrict__ boxes,
    const float* __restrict__ anch)
{
    const int lane = threadIdx.x;           // 0..31 = box index n
    const float4 bx = __ldg(boxes + b * 32 + lane);

    float acc[12];
    #pragma unroll
    for (int v = 0; v < 12; v++) acc[v] = 0.f;

    #pragma unroll
    for (int s = 0; s < 3; s++) {
        const float* pred = (s == 0) ? pr0 : ((s == 1) ? pr1 : pr2);
        const int   G  = (s == 0) ? G0 : ((s == 1) ? G1 : G2);
        const float Gf = (float)G;
        const int   HW = G * G;

        const float gx = bx.x * Gf, gy = bx.y * Gf;
        const float gw = bx.z * Gf, gh = bx.w * Gf;

        // anchor matching: argmax_a prod(min(r, 1/r)); first strict max wins
        int best = 0;
        float best_iou = -1.f, aw = 1.f, ah = 1.f;
        #pragma unroll
        for (int a = 0; a < 3; a++) {
            const float Aw = __ldg(anch + s * 6 + 2 * a);
            const float Ah = __ldg(anch + s * 6 + 2 * a + 1);
            const float iw = fminf(__fdividef(Aw, gw), __fdividef(gw, Aw));
            const float ih = fminf(__fdividef(Ah, gh), __fdividef(gh, Ah));
            const float io = iw * ih;
            if (io > best_iou) { best_iou = io; best = a; aw = Aw; ah = Ah; }
        }
        const int gi = (int)gx, gj = (int)gy;
        const int key = (best * G + gj) * G + gi;

        // dedup within the image: JAX scatter applies updates in order, so
        // the highest n (= highest lane) wins; n_pos counts unique cells.
        const unsigned m = __match_any_sync(0xffffffffu, key);
        if (lane == 31 - __clz(m)) {
            const int base = ((b * 18 + best * 6) * G + gj) * G + gi;
            const float q0 = __ldg(pred + base);
            const float q1 = __ldg(pred + base + HW);
            const float q2 = __ldg(pred + base + 2 * HW);
            const float q3 = __ldg(pred + base + 3 * HW);
            const float po = __ldg(pred + base + 4 * HW);

            const float tx = gx - (float)gi;
            const float ty = gy - (float)gj;
            const float tw = __logf(__fdividef(gw, aw) + 1e-16f);
            const float th = __logf(__fdividef(gh, ah) + 1e-16f);

            const float d0 = q0 - tx, d1 = q1 - ty, d2 = q2 - tw, d3 = q3 - th;
            acc[s]     += d0 * d0 + d1 * d1 + d2 * d2 + d3 * d3;
            acc[3 + s] += softplus_fast(-po);
            acc[6 + s] += softplus_fast(po);
            acc[9 + s] += 1.f;
        }
    }

    #pragma unroll
    for (int v = 0; v < 12; v++) {
        #pragma unroll
        for (int o = 16; o; o >>= 1)
            acc[v] += __shfl_xor_sync(0xffffffffu, acc[v], o);
    }
    if (lane == 0) {
        #pragma unroll
        for (int v = 0; v < 12; v++) g_sp[v * 64 + b] = acc[v];
    }
}

// ------------------------- K1: dense + sparse blocks -------------------------
__global__ void __launch_bounds__(NT2)
k_main(const float4* __restrict__ p0, const float4* __restrict__ p1,
       const float4* __restrict__ p2, const float4* __restrict__ boxes,
       const float* __restrict__ anch)
{
    if (blockIdx.x >= NB2) {
        if (threadIdx.x < 32)
            sparse_warp(blockIdx.x - NB2, (const float*)p0, (const float*)p1,
                        (const float*)p2, boxes, anch);
        return;
    }

    float a0 = 0.f, a1 = 0.f, a2 = 0.f;
    const int stride = NB2 * NT2;
    for (int f = blockIdx.x * NT2 + threadIdx.x; f < F4_TOT; f += stride) {
        if (f < F4_0) {
            int plane = f / HW4_0;
            int off   = f - plane * HW4_0;
            float4 v = __ldg(p0 + (plane * 6 + 4) * HW4_0 + off);
            a0 += sp_log2(v.x) + sp_log2(v.y) + sp_log2(v.z) + sp_log2(v.w);
        } else if (f < F4_0 + F4_1) {
            int g = f - F4_0;
            int plane = g / HW4_1;
            int off   = g - plane * HW4_1;
            float4 v = __ldg(p1 + (plane * 6 + 4) * HW4_1 + off);
            a1 += sp_log2(v.x) + sp_log2(v.y) + sp_log2(v.z) + sp_log2(v.w);
        } else {
            int g = f - (F4_0 + F4_1);
            int plane = g / HW4_2;
            int off   = g - plane * HW4_2;
            float4 v = __ldg(p2 + (plane * 6 + 4) * HW4_2 + off);
            a2 += sp_log2(v.x) + sp_log2(v.y) + sp_log2(v.z) + sp_log2(v.w);
        }
    }
    #pragma unroll
    for (int o = 16; o; o >>= 1) {
        a0 += __shfl_xor_sync(0xffffffffu, a0, o);
        a1 += __shfl_xor_sync(0xffffffffu, a1, o);
        a2 += __shfl_xor_sync(0xffffffffu, a2, o);
    }
    __shared__ float sh[3][NT2 / 32];
    int w = threadIdx.x >> 5, l = threadIdx.x & 31;
    if (l == 0) { sh[0][w] = a0; sh[1][w] = a1; sh[2][w] = a2; }
    __syncthreads();
    if (threadIdx.x == 0) {
        float s0 = 0.f, s1 = 0.f, s2 = 0.f;
        #pragma unroll
        for (int i = 0; i < NT2 / 32; i++) { s0 += sh[0][i]; s1 += sh[1][i]; s2 += sh[2][i]; }
        g_part[blockIdx.x * 3 + 0] = s0;
        g_part[blockIdx.x * 3 + 1] = s1;
        g_part[blockIdx.x * 3 + 2] = s2;
    }
}

// ------------------------- K2: final reduce ---------------------------------
__global__ void __launch_bounds__(512)
k_reduce(float* __restrict__ out)
{
    const int tid  = threadIdx.x;
    const int lane = tid & 31;
    const int warp = tid >> 5;   // 16 warps

    // dense partials: all threads
    float part[3] = {0.f, 0.f, 0.f};
    for (int i = tid; i < NB2; i += 512) {
        part[0] += g_part[3 * i + 0];
        part[1] += g_part[3 * i + 1];
        part[2] += g_part[3 * i + 2];
    }
    #pragma unroll
    for (int v = 0; v < 3; v++)
        #pragma unroll
        for (int o = 16; o; o >>= 1)
            part[v] += __shfl_xor_sync(0xffffffffu, part[v], o);

    __shared__ float sh_p[3][16];
    __shared__ float sh_s[12];
    if (lane == 0) {
        sh_p[0][warp] = part[0]; sh_p[1][warp] = part[1]; sh_p[2][warp] = part[2];
    }

    // sparse partials: warps 0..11, one value each over 64 images
    if (warp < 12) {
        float s = g_sp[warp * 64 + lane] + g_sp[warp * 64 + 32 + lane];
        #pragma unroll
        for (int o = 16; o; o >>= 1)
            s += __shfl_xor_sync(0xffffffffu, s, o);
        if (lane == 0) sh_s[warp] = s;
    }
    __syncthreads();

    if (tid == 0) {
        double P[3] = {0.0, 0.0, 0.0};
        #pragma unroll
        for (int i = 0; i < 16; i++) {
            P[0] += (double)sh_p[0][i];
            P[1] += (double)sh_p[1][i];
            P[2] += (double)sh_p[2][i];
        }
        const double T[3] = {4915200.0, 1228800.0, 307200.0};
        double lbox = 0.0, lobj = 0.0;
        #pragma unroll
        for (int s = 0; s < 3; s++) {
            const double sq   = (double)sh_s[s];
            const double spn  = (double)sh_s[3 + s];
            const double spp  = (double)sh_s[6 + s];
            const double npos = (double)sh_s[9 + s];
            const double nneg = T[s] - npos;
            const double all_sp = P[s] * 0.6931471805599453;  // log2 -> ln
            lobj += spn / npos + (all_sp - spp) / nneg;
            lbox += sq / npos;
        }
        out[0] = (float)(0.05 * lbox + 1.0 * lobj);
    }
}

extern "C" void kernel_launch(void* const* d_in, const int* in_sizes, int n_in,
                              void* d_out, int out_size)
{
    (void)in_sizes; (void)n_in; (void)out_size;
    const float* pred0 = (const float*)d_in[0];
    const float* pred1 = (const float*)d_in[1];
    const float* pred2 = (const float*)d_in[2];
    const float* boxes = (const float*)d_in[3];
    // d_in[4] = labels (unused, nc == 1)
    const float* anch  = (const float*)d_in[5];
    float* out = (float*)d_out;

    k_main<<<NB2 + 64, NT2>>>((const float4*)pred0, (const float4*)pred1,
                              (const float4*)pred2, (const float4*)boxes, anch);
    k_reduce<<<1, 512>>>(out);
}

// round 6
// speedup vs baseline: 2.4767x; 1.6290x over previous
#include <cuda_runtime.h>
#include <cuda_bf16.h>
#include <math.h>

// ---------------------------------------------------------------------------
// YOLO v5 loss (nc=1): B=64, N=32, A=3, grids 160/80/40, channels A*(5+1)=18.
//   K1: blocks [0,896)      dense softplus, scale-0 obj plane
//       blocks [896,1120)   dense softplus, scale-1 obj plane
//       blocks [1120,1184)  dense softplus, scale-2 obj plane
//       blocks [1184,1248)  1 warp each: sparse targets for one batch image
//   K2: single block, fp32 fold of dense + sparse partials.
// ---------------------------------------------------------------------------

#define NB_S0 896
#define NB_S1 224
#define NB_S2 64
#define NB2   (NB_S0 + NB_S1 + NB_S2)   // 1184 dense blocks
#define NT2   256

#define G0 160
#define G1 80
#define G2 40
#define HW4_0 6400        // (160*160)/4
#define HW4_1 1600
#define HW4_2 400
#define F4_0 1228800      // 64*3*HW4_0
#define F4_1 307200
#define F4_2 76800

__device__ float g_part[NB2];       // dense per-block partial sums (log2 units)
__device__ float g_sp[12 * 64];     // sparse per-image sums, SoA [12][64]
// v: 0..2 sq, 3..5 spn, 6..8 spp, 9..11 npos (per scale)

__device__ __forceinline__ float sp_log2(float x) {
    // log2(1 + exp(x)); |x| <~ 6 for N(0,1) inputs
    float e, l;
    asm("ex2.approx.ftz.f32 %0, %1;" : "=f"(e) : "f"(x * 1.4426950408889634f));
    asm("lg2.approx.ftz.f32 %0, %1;" : "=f"(l) : "f"(1.0f + e));
    return l;
}

__device__ __forceinline__ float softplus_fast(float x) {
    return sp_log2(x) * 0.6931471805599453f;   // ln2
}

// ------------------------- sparse: one warp = one image ---------------------
__device__ __forceinline__ void sparse_warp(
    int b, const float* __restrict__ pr0, const float* __restrict__ pr1,
    const float* __restrict__ pr2, const float4* __restrict__ boxes,
    const float* __restrict__ anch)
{
    const int lane = threadIdx.x;           // 0..31 = box index n
    const float4 bx = __ldg(boxes + b * 32 + lane);

    float acc[12];
    #pragma unroll
    for (int v = 0; v < 12; v++) acc[v] = 0.f;

    #pragma unroll
    for (int s = 0; s < 3; s++) {
        const float* pred = (s == 0) ? pr0 : ((s == 1) ? pr1 : pr2);
        const int   G  = (s == 0) ? G0 : ((s == 1) ? G1 : G2);
        const float Gf = (float)G;
        const int   HW = G * G;

        const float gx = bx.x * Gf, gy = bx.y * Gf;
        const float gw = bx.z * Gf, gh = bx.w * Gf;

        // anchor matching: argmax_a prod(min(r, 1/r)); first strict max wins
        int best = 0;
        float best_iou = -1.f, aw = 1.f, ah = 1.f;
        #pragma unroll
        for (int a = 0; a < 3; a++) {
            const float Aw = __ldg(anch + s * 6 + 2 * a);
            const float Ah = __ldg(anch + s * 6 + 2 * a + 1);
            const float iw = fminf(__fdividef(Aw, gw), __fdividef(gw, Aw));
            const float ih = fminf(__fdividef(Ah, gh), __fdividef(gh, Ah));
            const float io = iw * ih;
            if (io > best_iou) { best_iou = io; best = a; aw = Aw; ah = Ah; }
        }
        const int gi = (int)gx, gj = (int)gy;
        const int key = (best * G + gj) * G + gi;

        // dedup within the image: JAX scatter applies updates in order, so
        // the highest n (= highest lane) wins; n_pos counts unique cells.
        const unsigned m = __match_any_sync(0xffffffffu, key);
        if (lane == 31 - __clz(m)) {
            const int base = ((b * 18 + best * 6) * G + gj) * G + gi;
            const float q0 = __ldg(pred + base);
            const float q1 = __ldg(pred + base + HW);
            const float q2 = __ldg(pred + base + 2 * HW);
            const float q3 = __ldg(pred + base + 3 * HW);
            const float po = __ldg(pred + base + 4 * HW);

            const float tx = gx - (float)gi;
            const float ty = gy - (float)gj;
            const float tw = __logf(__fdividef(gw, aw) + 1e-16f);
            const float th = __logf(__fdividef(gh, ah) + 1e-16f);

            const float d0 = q0 - tx, d1 = q1 - ty, d2 = q2 - tw, d3 = q3 - th;
            acc[s]     += d0 * d0 + d1 * d1 + d2 * d2 + d3 * d3;
            acc[3 + s] += softplus_fast(-po);
            acc[6 + s] += softplus_fast(po);
            acc[9 + s] += 1.f;
        }
    }

    #pragma unroll
    for (int v = 0; v < 12; v++) {
        #pragma unroll
        for (int o = 16; o; o >>= 1)
            acc[v] += __shfl_xor_sync(0xffffffffu, acc[v], o);
    }
    if (lane == 0) {
        #pragma unroll
        for (int v = 0; v < 12; v++) g_sp[v * 64 + b] = acc[v];
    }
}

// dense worker: grid-stride over one scale's obj elements, 2x unrolled
__device__ __forceinline__ float dense_sum(
    const float4* __restrict__ p, int hw4, int f4_tot, int rank, int nblocks)
{
    float a = 0.f;
    const int stride = nblocks * NT2;
    int f = rank * NT2 + (int)threadIdx.x;
    for (; f + stride < f4_tot; f += 2 * stride) {
        const int p1 = f / hw4;                 // const divisor per call site
        const int f2 = f + stride;
        const int p2 = f2 / hw4;
        float4 v1 = __ldg(p + (p1 * 6 + 4) * hw4 + (f - p1 * hw4));
        float4 v2 = __ldg(p + (p2 * 6 + 4) * hw4 + (f2 - p2 * hw4));
        a += sp_log2(v1.x) + sp_log2(v1.y) + sp_log2(v1.z) + sp_log2(v1.w);
        a += sp_log2(v2.x) + sp_log2(v2.y) + sp_log2(v2.z) + sp_log2(v2.w);
    }
    if (f < f4_tot) {
        const int pl = f / hw4;
        float4 v = __ldg(p + (pl * 6 + 4) * hw4 + (f - pl * hw4));
        a += sp_log2(v.x) + sp_log2(v.y) + sp_log2(v.z) + sp_log2(v.w);
    }
    return a;
}

// ------------------------- K1: dense + sparse blocks -------------------------
__global__ void __launch_bounds__(NT2)
k_main(const float4* __restrict__ p0, const float4* __restrict__ p1,
       const float4* __restrict__ p2, const float4* __restrict__ boxes,
       const float* __restrict__ anch)
{
    const int blk = blockIdx.x;
    if (blk >= NB2) {
        if (threadIdx.x < 32)
            sparse_warp(blk - NB2, (const float*)p0, (const float*)p1,
                        (const float*)p2, boxes, anch);
        return;
    }

    float a;
    if (blk < NB_S0)
        a = dense_sum(p0, HW4_0, F4_0, blk, NB_S0);
    else if (blk < NB_S0 + NB_S1)
        a = dense_sum(p1, HW4_1, F4_1, blk - NB_S0, NB_S1);
    else
        a = dense_sum(p2, HW4_2, F4_2, blk - NB_S0 - NB_S1, NB_S2);

    #pragma unroll
    for (int o = 16; o; o >>= 1)
        a += __shfl_xor_sync(0xffffffffu, a, o);

    __shared__ float sh[NT2 / 32];
    const int w = threadIdx.x >> 5, l = threadIdx.x & 31;
    if (l == 0) sh[w] = a;
    __syncthreads();
    if (threadIdx.x == 0) {
        float s = 0.f;
        #pragma unroll
        for (int i = 0; i < NT2 / 32; i++) s += sh[i];
        g_part[blk] = s;
    }
}

// ------------------------- K2: final reduce (all fp32) -----------------------
__global__ void __launch_bounds__(512)
k_reduce(float* __restrict__ out)
{
    const int tid  = threadIdx.x;
    const int lane = tid & 31;
    const int warp = tid >> 5;   // 16 warps

    // dense partials, per scale (block ranges are contiguous per scale)
    float part[3] = {0.f, 0.f, 0.f};
    for (int i = tid; i < NB2; i += 512) {
        const float v = g_part[i];
        if (i < NB_S0)                 part[0] += v;
        else if (i < NB_S0 + NB_S1)    part[1] += v;
        else                           part[2] += v;
    }
    #pragma unroll
    for (int v = 0; v < 3; v++)
        #pragma unroll
        for (int o = 16; o; o >>= 1)
            part[v] += __shfl_xor_sync(0xffffffffu, part[v], o);

    __shared__ float sh_p[3][16];
    __shared__ float sh_s[12];
    if (lane == 0) {
        sh_p[0][warp] = part[0]; sh_p[1][warp] = part[1]; sh_p[2][warp] = part[2];
    }

    // sparse partials: warps 0..11, one value each over 64 images
    if (warp < 12) {
        float s = g_sp[warp * 64 + lane] + g_sp[warp * 64 + 32 + lane];
        #pragma unroll
        for (int o = 16; o; o >>= 1)
            s += __shfl_xor_sync(0xffffffffu, s, o);
        if (lane == 0) sh_s[warp] = s;
    }
    __syncthreads();

    if (tid == 0) {
        float P[3] = {0.f, 0.f, 0.f};
        #pragma unroll
        for (int i = 0; i < 16; i++) {
            P[0] += sh_p[0][i]; P[1] += sh_p[1][i]; P[2] += sh_p[2][i];
        }
        const float T[3] = {4915200.f, 1228800.f, 307200.f};
        float lbox = 0.f, lobj = 0.f;
        #pragma unroll
        for (int s = 0; s < 3; s++) {
            const float sq   = sh_s[s];
            const float spn  = sh_s[3 + s];
            const float spp  = sh_s[6 + s];
            const float npos = sh_s[9 + s];
            const float nneg = T[s] - npos;
            const float all_sp = P[s] * 0.6931471805599453f;  // log2 -> ln
            lobj += spn / npos + (all_sp - spp) / nneg;
            lbox += sq / npos;
        }
        out[0] = 0.05f * lbox + lobj;
    }
}

extern "C" void kernel_launch(void* const* d_in, const int* in_sizes, int n_in,
                              void* d_out, int out_size)
{
    (void)in_sizes; (void)n_in; (void)out_size;
    const float* pred0 = (const float*)d_in[0];
    const float* pred1 = (const float*)d_in[1];
    const float* pred2 = (const float*)d_in[2];
    const float* boxes = (const float*)d_in[3];
    // d_in[4] = labels (unused, nc == 1)
    const float* anch  = (const float*)d_in[5];
    float* out = (float*)d_out;

    k_main<<<NB2 + 64, NT2>>>((const float4*)pred0, (const float4*)pred1,
                              (const float4*)pred2, (const float4*)boxes, anch);
    k_reduce<<<1, 512>>>(out);
}